// round 1
// baseline (speedup 1.0000x reference)
#include <cuda_runtime.h>
#include <math.h>

// (B*C) channels, D slices, H*W voxels per slice
#define CHN   64
#define DD    96
#define HWN   16384      // 128*128
#define SL_F4 4096       // HWN / 4

// Scratch: per-channel [mass, wx, wy, wz] accumulated in double.
__device__ double g_acc[CHN][4];

__global__ void zero_acc_kernel() {
    int i = threadIdx.x;
    if (i < CHN * 4) ((double*)g_acc)[i] = 0.0;
}

__global__ __launch_bounds__(256) void reduce_slices_kernel(const float* __restrict__ seg) {
    const int slice = blockIdx.x;        // 0 .. 6143  == bc*96 + d
    const int bc = slice / DD;
    const int d  = slice - bc * DD;
    const float4* __restrict__ p = (const float4*)(seg + (size_t)slice * HWN);

    float mass = 0.f, wx = 0.f, wy = 0.f;
    for (int i = threadIdx.x; i < SL_F4; i += 256) {
        float4 v = p[i];
        int base = i << 2;                       // linear idx of v.x within slice
        float h  = (float)(base >> 7);           // row (H index) — constant across the 4
        float w0 = (float)(base & 127);          // col (W index) of v.x
        float s4 = (v.x + v.y) + (v.z + v.w);
        float t  = v.y + 2.f * v.z + 3.f * v.w;  // Σ v_k * k   (k = 0..3 offset)
        mass += s4;
        wy   += s4 * h;
        wx   += s4 * w0 + t;
    }

    // warp reduce
    for (int o = 16; o; o >>= 1) {
        mass += __shfl_down_sync(0xffffffffu, mass, o);
        wx   += __shfl_down_sync(0xffffffffu, wx,   o);
        wy   += __shfl_down_sync(0xffffffffu, wy,   o);
    }
    __shared__ float sm[3][8];
    int lane = threadIdx.x & 31, warp = threadIdx.x >> 5;
    if (lane == 0) { sm[0][warp] = mass; sm[1][warp] = wx; sm[2][warp] = wy; }
    __syncthreads();
    if (warp == 0) {
        mass = (lane < 8) ? sm[0][lane] : 0.f;
        wx   = (lane < 8) ? sm[1][lane] : 0.f;
        wy   = (lane < 8) ? sm[2][lane] : 0.f;
        for (int o = 4; o; o >>= 1) {
            mass += __shfl_down_sync(0xffffffffu, mass, o);
            wx   += __shfl_down_sync(0xffffffffu, wx,   o);
            wy   += __shfl_down_sync(0xffffffffu, wy,   o);
        }
        if (lane == 0) {
            atomicAdd(&g_acc[bc][0], (double)mass);
            atomicAdd(&g_acc[bc][1], (double)wx);
            atomicAdd(&g_acc[bc][2], (double)wy);
            atomicAdd(&g_acc[bc][3], (double)mass * (double)d);
        }
    }
}

__global__ void finalize_kernel(float* __restrict__ out) {
    if (threadIdx.x != 0 || blockIdx.x != 0) return;

    // ---- centers & volumes ----
    double ctr[2][32][3];
    double vol[2][32];
    for (int b = 0; b < 2; b++)
        for (int c = 0; c < 32; c++) {
            const double* a = g_acc[b * 32 + c];
            double m = a[0];
            vol[b][c] = m;
            double safe = (m > 0.0) ? m : 1.0;
            double cx = a[1] / safe / 128.0;
            double cy = a[2] / safe / 128.0;
            double cz = a[3] / safe /  96.0;
            if (!(m > 0.0)) { cx = 0.0; cy = 0.0; cz = 0.0; }
            ctr[b][c][0] = cx; ctr[b][c][1] = cy; ctr[b][c][2] = cz;
        }

    // ---- expected positions ----
    double expv[32][3];
    const double PI = 3.14159265358979323846;
    for (int i = 0; i < 16; i++) {
        double ua = -PI / 2.0 + (double)i * (PI / 15.0);
        expv[i][0] = 0.6 * cos(ua);
        expv[i][1] = 0.6 * sin(ua);
        expv[i][2] = 0.7;
        double la = PI / 2.0 - (double)i * (PI / 15.0);
        expv[16 + i][0] = 0.55 * cos(la);
        expv[16 + i][1] = 0.55 * sin(la);
        expv[16 + i][2] = 0.3;
    }

    // ---- landmark ----
    double landmark = 0.0;
    for (int b = 0; b < 2; b++)
        for (int c = 0; c < 32; c++)
            for (int k = 0; k < 3; k++) {
                double dlt = ctr[b][c][k] - expv[c][k];
                landmark += dlt * dlt;
            }
    landmark /= (2.0 * 32.0 * 3.0);

    // ---- adjacency pairs (0-indexed firsts) ----
    const int adjF[28] = {0,1,2,3,4,5,6, 8,9,10,11,12,13,14,
                          16,17,18,19,20,21,22, 24,25,26,27,28,29,30};
    // ---- opposing / symmetric pairs ----
    const int o1[16] = {0,1,2,3,4,5,6,7, 16,17,18,19,20,21,22,23};
    const int o2[16] = {15,14,13,12,11,10,9,8, 31,30,29,28,27,26,25,24};

    // ---- spatial ----
    double spatial = 0.0;
    for (int p = 0; p < 28; p++) {
        int i = adjF[p], j = adjF[p] + 1;
        for (int b = 0; b < 2; b++) {
            double dx = ctr[b][i][0] - ctr[b][j][0];
            double dy = ctr[b][i][1] - ctr[b][j][1];
            double dz = ctr[b][i][2] - ctr[b][j][2];
            double dist = sqrt(dx * dx + dy * dy + dz * dz);
            double r = dist - 0.1;
            if (r > 0.0) spatial += r * 0.5;     // mean over batch
        }
    }
    double xy_loss = 0.0, z_loss = 0.0;
    for (int p = 0; p < 16; p++) {
        int i = o1[p], j = o2[p];
        for (int b = 0; b < 2; b++) {
            double dx = ctr[b][i][0] - ctr[b][j][0];
            double dy = ctr[b][i][1] - ctr[b][j][1];
            double dz = ctr[b][i][2] - ctr[b][j][2];
            xy_loss += (dx * dx + dy * dy) * 0.25;   // mean over (batch=2, coords=2)
            double r = 0.3 - fabs(dz);
            if (r > 0.0) z_loss += r * 0.5;          // mean over batch
        }
    }
    spatial += xy_loss + z_loss;

    // ---- symmetry ----
    double yz_loss = 0.0, x_loss = 0.0;
    for (int p = 0; p < 16; p++) {
        int i = o1[p], j = o2[p];
        for (int b = 0; b < 2; b++) {
            double dy = ctr[b][i][1] - ctr[b][j][1];
            double dz = ctr[b][i][2] - ctr[b][j][2];
            yz_loss += (dy * dy + dz * dz) * 0.25;   // mean over (batch, 2 coords)
            double sx = ctr[b][i][0] + ctr[b][j][0];
            x_loss  += sx * sx * 0.5;                // mean over batch
        }
    }
    double symmetry = yz_loss + x_loss;

    // ---- anatomy: per-group channel variance (ddof=1), mean over batch ----
    const int g0[8]  = {6,7,8,9,22,23,24,25};
    const int g1[4]  = {5,10,21,26};
    const int g2[8]  = {3,4,11,12,19,20,27,28};
    const int g3[12] = {0,1,2,13,14,15,16,17,18,29,30,31};
    const int* groups[4] = {g0, g1, g2, g3};
    const int gn[4] = {8, 4, 8, 12};

    double anatomy = 0.0;
    for (int g = 0; g < 4; g++) {
        const int* idx = groups[g];
        int n = gn[g];
        double mb = 0.0;                 // accumulates mean-over-batch of var
        for (int b = 0; b < 2; b++) {
            double mean = 0.0;
            for (int k = 0; k < n; k++) mean += vol[b][idx[k]];
            mean /= (double)n;
            double ss = 0.0;
            for (int k = 0; k < n; k++) {
                double dv = vol[b][idx[k]] - mean;
                ss += dv * dv;
            }
            mb += ss / (double)(n - 1);
        }
        anatomy += mb * 0.5;
    }

    // ---- weights & total ----
    landmark *= 10.0;
    spatial  *=  5.0;
    symmetry *=  3.0;
    anatomy  *=  7.0;
    double total = landmark + spatial + symmetry + anatomy;

    out[0] = (float)landmark;
    out[1] = (float)spatial;
    out[2] = (float)symmetry;
    out[3] = (float)anatomy;
    out[4] = (float)total;
}

extern "C" void kernel_launch(void* const* d_in, const int* in_sizes, int n_in,
                              void* d_out, int out_size) {
    const float* seg = (const float*)d_in[0];
    float* out = (float*)d_out;
    (void)in_sizes; (void)n_in; (void)out_size;

    zero_acc_kernel<<<1, 256>>>();
    reduce_slices_kernel<<<CHN * DD, 256>>>(seg);
    finalize_kernel<<<1, 1>>>(out);
}

// round 2
// speedup vs baseline: 1.3400x; 1.3400x over previous
#include <cuda_runtime.h>
#include <math.h>

#define CHN   64        // B*C
#define DD    96        // depth slices per channel
#define HWN   16384     // 128*128 voxels per slice
#define SL_F4 4096      // HWN/4
#define NSLICE (CHN*DD) // 6144

// Per-slice partials: [mass, wx, wy] (wz = mass*d reconstructed in finalize).
__device__ float g_part[NSLICE][3];

__global__ __launch_bounds__(256) void reduce_slices_kernel(const float* __restrict__ seg) {
    const int slice = blockIdx.x;                 // bc*96 + d
    const int tid = threadIdx.x;
    const float4* __restrict__ p = (const float4*)(seg + (size_t)slice * HWN) + tid;

    // Separable per-thread weights:
    //   element linear index = 4*(tid + 256k); 4*tid < 1024, 1024k aligned to 128
    //   col w of first elem  = (4*tid) & 127            (constant per thread)
    //   row h                = (tid>>5) + 8k
    const float w0 = (float)((4 * tid) & 127);
    const float h0 = (float)(tid >> 5);

    float m = 0.f, u = 0.f, ts = 0.f;
#pragma unroll
    for (int k = 0; k < 16; k++) {
        float4 v = p[k * 256];
        float s4 = (v.x + v.y) + (v.z + v.w);
        float t  = fmaf(3.f, v.w, fmaf(2.f, v.z, v.y));   // sub-column offsets
        m  += s4;
        u   = fmaf((float)k, s4, u);                      // for row weight
        ts += t;
    }
    float wx = fmaf(w0, m, ts);
    float wy = fmaf(h0, m, 8.f * u);

    // warp reduce
    for (int o = 16; o; o >>= 1) {
        m  += __shfl_down_sync(0xffffffffu, m,  o);
        wx += __shfl_down_sync(0xffffffffu, wx, o);
        wy += __shfl_down_sync(0xffffffffu, wy, o);
    }
    __shared__ float sm[3][8];
    int lane = tid & 31, warp = tid >> 5;
    if (lane == 0) { sm[0][warp] = m; sm[1][warp] = wx; sm[2][warp] = wy; }
    __syncthreads();
    if (warp == 0) {
        m  = (lane < 8) ? sm[0][lane] : 0.f;
        wx = (lane < 8) ? sm[1][lane] : 0.f;
        wy = (lane < 8) ? sm[2][lane] : 0.f;
        for (int o = 4; o; o >>= 1) {
            m  += __shfl_down_sync(0xffffffffu, m,  o);
            wx += __shfl_down_sync(0xffffffffu, wx, o);
            wy += __shfl_down_sync(0xffffffffu, wy, o);
        }
        if (lane == 0) {
            g_part[slice][0] = m;
            g_part[slice][1] = wx;
            g_part[slice][2] = wy;
        }
    }
}

// cos/sin of (-90 + 12*i) degrees, i = 0..15
__device__ const double COSV[16] = {
    0.0, 0.20791169081775934, 0.40673664307580021, 0.58778525229247314,
    0.74314482547739424, 0.86602540378443865, 0.95105651629515353, 0.99452189536827329,
    0.99452189536827329, 0.95105651629515353, 0.86602540378443865, 0.74314482547739424,
    0.58778525229247314, 0.40673664307580021, 0.20791169081775934, 0.0 };
__device__ const double SINV[16] = {
   -1.0, -0.97814760073380558, -0.91354545764260087, -0.80901699437494745,
   -0.66913060635885824, -0.5, -0.30901699437494742, -0.10452846326765347,
    0.10452846326765347, 0.30901699437494742, 0.5, 0.66913060635885824,
    0.80901699437494745, 0.91354545764260087, 0.97814760073380558, 1.0 };

__global__ void finalize_kernel(float* __restrict__ out) {
    __shared__ double sctr[CHN][3];
    __shared__ double svol[CHN];
    const int t = threadIdx.x;

    if (t < CHN) {
        double m = 0.0, wx = 0.0, wy = 0.0, wz = 0.0;
        const float* q = &g_part[t * DD][0];
        for (int d = 0; d < DD; d++) {
            double md = (double)q[3 * d + 0];
            m  += md;
            wx += (double)q[3 * d + 1];
            wy += (double)q[3 * d + 2];
            wz += md * (double)d;
        }
        svol[t] = m;
        double safe = (m > 0.0) ? m : 1.0;
        double cx = wx / safe / 128.0;
        double cy = wy / safe / 128.0;
        double cz = wz / safe /  96.0;
        if (!(m > 0.0)) { cx = 0.0; cy = 0.0; cz = 0.0; }
        sctr[t][0] = cx; sctr[t][1] = cy; sctr[t][2] = cz;
    }
    __syncthreads();
    if (t != 0) return;

    // expected positions
    double expv[32][3];
    for (int i = 0; i < 16; i++) {
        expv[i][0] = 0.6 * COSV[i];
        expv[i][1] = 0.6 * SINV[i];
        expv[i][2] = 0.7;
        expv[16 + i][0] = 0.55 * COSV[15 - i];
        expv[16 + i][1] = 0.55 * SINV[15 - i];
        expv[16 + i][2] = 0.3;
    }

    // landmark
    double landmark = 0.0;
    for (int b = 0; b < 2; b++)
        for (int c = 0; c < 32; c++)
            for (int k = 0; k < 3; k++) {
                double dlt = sctr[b * 32 + c][k] - expv[c][k];
                landmark += dlt * dlt;
            }
    landmark /= 192.0;

    const int adjF[28] = {0,1,2,3,4,5,6, 8,9,10,11,12,13,14,
                          16,17,18,19,20,21,22, 24,25,26,27,28,29,30};
    const int o1[16] = {0,1,2,3,4,5,6,7, 16,17,18,19,20,21,22,23};
    const int o2[16] = {15,14,13,12,11,10,9,8, 31,30,29,28,27,26,25,24};

    // spatial
    double spatial = 0.0;
    for (int p = 0; p < 28; p++) {
        int i = adjF[p], j = i + 1;
        for (int b = 0; b < 2; b++) {
            const double* A = sctr[b * 32 + i];
            const double* Bp = sctr[b * 32 + j];
            double dx = A[0] - Bp[0], dy = A[1] - Bp[1], dz = A[2] - Bp[2];
            double r = sqrt(dx * dx + dy * dy + dz * dz) - 0.1;
            if (r > 0.0) spatial += r * 0.5;
        }
    }
    double xy_loss = 0.0, z_loss = 0.0, yz_loss = 0.0, x_loss = 0.0;
    for (int p = 0; p < 16; p++) {
        for (int b = 0; b < 2; b++) {
            const double* A = sctr[b * 32 + o1[p]];
            const double* Bp = sctr[b * 32 + o2[p]];
            double dx = A[0] - Bp[0], dy = A[1] - Bp[1], dz = A[2] - Bp[2];
            xy_loss += (dx * dx + dy * dy) * 0.25;
            double r = 0.3 - fabs(dz);
            if (r > 0.0) z_loss += r * 0.5;
            yz_loss += (dy * dy + dz * dz) * 0.25;
            double sx = A[0] + Bp[0];
            x_loss += sx * sx * 0.5;
        }
    }
    spatial += xy_loss + z_loss;
    double symmetry = yz_loss + x_loss;

    // anatomy: per-group variance over channels (ddof=1), mean over batch
    const int g0[8]  = {6,7,8,9,22,23,24,25};
    const int g1[4]  = {5,10,21,26};
    const int g2[8]  = {3,4,11,12,19,20,27,28};
    const int g3[12] = {0,1,2,13,14,15,16,17,18,29,30,31};
    const int* groups[4] = {g0, g1, g2, g3};
    const int gn[4] = {8, 4, 8, 12};

    double anatomy = 0.0;
    for (int g = 0; g < 4; g++) {
        const int* idx = groups[g];
        int n = gn[g];
        for (int b = 0; b < 2; b++) {
            double mean = 0.0;
            for (int k = 0; k < n; k++) mean += svol[b * 32 + idx[k]];
            mean /= (double)n;
            double ss = 0.0;
            for (int k = 0; k < n; k++) {
                double dv = svol[b * 32 + idx[k]] - mean;
                ss += dv * dv;
            }
            anatomy += ss / (double)(n - 1) * 0.5;
        }
    }

    landmark *= 10.0;
    spatial  *=  5.0;
    symmetry *=  3.0;
    anatomy  *=  7.0;
    double total = landmark + spatial + symmetry + anatomy;

    out[0] = (float)landmark;
    out[1] = (float)spatial;
    out[2] = (float)symmetry;
    out[3] = (float)anatomy;
    out[4] = (float)total;
}

extern "C" void kernel_launch(void* const* d_in, const int* in_sizes, int n_in,
                              void* d_out, int out_size) {
    const float* seg = (const float*)d_in[0];
    float* out = (float*)d_out;
    (void)in_sizes; (void)n_in; (void)out_size;

    reduce_slices_kernel<<<NSLICE, 256>>>(seg);
    finalize_kernel<<<1, 256>>>(out);
}

// round 3
// speedup vs baseline: 3.2022x; 2.3898x over previous
#include <cuda_runtime.h>
#include <math.h>

#define CHN   64        // B*C
#define DD    96        // depth slices per channel
#define HWN   16384     // 128*128 voxels per slice
#define NSLICE (CHN*DD) // 6144

// Per-slice partials: [mass, wx, wy] (wz = mass*d reconstructed in finalize).
__device__ float g_part[NSLICE][3];

__global__ __launch_bounds__(256) void reduce_slices_kernel(const float* __restrict__ seg) {
    const int slice = blockIdx.x;                 // bc*96 + d
    const int tid = threadIdx.x;
    const float4* __restrict__ p = (const float4*)(seg + (size_t)slice * HWN) + tid;

    // Separable per-thread weights:
    //   element linear index = 4*(tid + 256k)
    //   col w of first elem  = (4*tid) & 127  (constant per thread)
    //   row h                = (tid>>5) + 8k
    const float w0 = (float)((4 * tid) & 127);
    const float h0 = (float)(tid >> 5);

    float m = 0.f, u = 0.f, ts = 0.f;
#pragma unroll
    for (int k = 0; k < 16; k++) {
        float4 v = p[k * 256];
        float s4 = (v.x + v.y) + (v.z + v.w);
        float t  = fmaf(3.f, v.w, fmaf(2.f, v.z, v.y));
        m  += s4;
        u   = fmaf((float)k, s4, u);
        ts += t;
    }
    float wx = fmaf(w0, m, ts);
    float wy = fmaf(h0, m, 8.f * u);

    for (int o = 16; o; o >>= 1) {
        m  += __shfl_down_sync(0xffffffffu, m,  o);
        wx += __shfl_down_sync(0xffffffffu, wx, o);
        wy += __shfl_down_sync(0xffffffffu, wy, o);
    }
    __shared__ float sm[3][8];
    int lane = tid & 31, warp = tid >> 5;
    if (lane == 0) { sm[0][warp] = m; sm[1][warp] = wx; sm[2][warp] = wy; }
    __syncthreads();
    if (warp == 0) {
        m  = (lane < 8) ? sm[0][lane] : 0.f;
        wx = (lane < 8) ? sm[1][lane] : 0.f;
        wy = (lane < 8) ? sm[2][lane] : 0.f;
        for (int o = 4; o; o >>= 1) {
            m  += __shfl_down_sync(0xffffffffu, m,  o);
            wx += __shfl_down_sync(0xffffffffu, wx, o);
            wy += __shfl_down_sync(0xffffffffu, wy, o);
        }
        if (lane == 0) {
            g_part[slice][0] = m;
            g_part[slice][1] = wx;
            g_part[slice][2] = wy;
        }
    }
}

// cos/sin of (-90 + 12*i) degrees, i = 0..15 (fp32 literals)
__device__ const float COSV[16] = {
    0.0f, 0.20791169f, 0.40673664f, 0.58778525f,
    0.74314483f, 0.86602540f, 0.95105652f, 0.99452190f,
    0.99452190f, 0.95105652f, 0.86602540f, 0.74314483f,
    0.58778525f, 0.40673664f, 0.20791169f, 0.0f };
__device__ const float SINV[16] = {
   -1.0f, -0.97814760f, -0.91354546f, -0.80901699f,
   -0.66913061f, -0.5f, -0.30901699f, -0.10452846f,
    0.10452846f, 0.30901699f, 0.5f, 0.66913061f,
    0.80901699f, 0.91354546f, 0.97814760f, 1.0f };

__global__ void finalize_kernel(float* __restrict__ out) {
    __shared__ float  sctr[CHN][3];
    __shared__ double svol[CHN];
    const int t = threadIdx.x;

    // Per-channel reduction over 96 slices: FP64 adds/muls only (pipelined, cheap).
    if (t < CHN) {
        double m = 0.0, wx = 0.0, wy = 0.0, wz = 0.0;
        const float* q = &g_part[t * DD][0];
        for (int d = 0; d < DD; d++) {
            double md = (double)q[3 * d + 0];
            m  += md;
            wx += (double)q[3 * d + 1];
            wy += (double)q[3 * d + 2];
            wz += md * (double)d;
        }
        svol[t] = m;
        // ONE fp64 division per thread, all 64 in parallel.
        double inv = (m > 0.0) ? (1.0 / m) : 0.0;
        sctr[t][0] = (float)(wx * inv * (1.0 / 128.0));
        sctr[t][1] = (float)(wy * inv * (1.0 / 128.0));
        sctr[t][2] = (float)(wz * inv * (1.0 /  96.0));
    }
    __syncthreads();
    if (t != 0) return;

    // ---- all loss math in fp32 (matches reference precision) ----
    float landmark = 0.f;
    for (int c = 0; c < 32; c++) {
        float ex = (c < 16) ? 0.6f * COSV[c] : 0.55f * COSV[31 - c];
        float ey = (c < 16) ? 0.6f * SINV[c] : 0.55f * SINV[31 - c];
        float ez = (c < 16) ? 0.7f : 0.3f;
        for (int b = 0; b < 2; b++) {
            const float* A = sctr[b * 32 + c];
            float dx = A[0] - ex, dy = A[1] - ey, dz = A[2] - ez;
            landmark += dx * dx + dy * dy + dz * dz;
        }
    }
    landmark *= (1.f / 192.f);

    const int adjF[28] = {0,1,2,3,4,5,6, 8,9,10,11,12,13,14,
                          16,17,18,19,20,21,22, 24,25,26,27,28,29,30};
    const int o1[16] = {0,1,2,3,4,5,6,7, 16,17,18,19,20,21,22,23};
    const int o2[16] = {15,14,13,12,11,10,9,8, 31,30,29,28,27,26,25,24};

    float spatial = 0.f;
    for (int p = 0; p < 28; p++) {
        int i = adjF[p], j = i + 1;
        for (int b = 0; b < 2; b++) {
            const float* A = sctr[b * 32 + i];
            const float* Bp = sctr[b * 32 + j];
            float dx = A[0] - Bp[0], dy = A[1] - Bp[1], dz = A[2] - Bp[2];
            float r = sqrtf(dx * dx + dy * dy + dz * dz) - 0.1f;
            if (r > 0.f) spatial += r * 0.5f;
        }
    }
    float xy_loss = 0.f, z_loss = 0.f, yz_loss = 0.f, x_loss = 0.f;
    for (int p = 0; p < 16; p++) {
        for (int b = 0; b < 2; b++) {
            const float* A = sctr[b * 32 + o1[p]];
            const float* Bp = sctr[b * 32 + o2[p]];
            float dx = A[0] - Bp[0], dy = A[1] - Bp[1], dz = A[2] - Bp[2];
            xy_loss += (dx * dx + dy * dy) * 0.25f;
            float r = 0.3f - fabsf(dz);
            if (r > 0.f) z_loss += r * 0.5f;
            yz_loss += (dy * dy + dz * dz) * 0.25f;
            float sx = A[0] + Bp[0];
            x_loss += sx * sx * 0.5f;
        }
    }
    spatial += xy_loss + z_loss;
    float symmetry = yz_loss + x_loss;

    // ---- anatomy in fp64, but divisions replaced by reciprocal-constant DMULs ----
    const int g0[8]  = {6,7,8,9,22,23,24,25};
    const int g1[4]  = {5,10,21,26};
    const int g2[8]  = {3,4,11,12,19,20,27,28};
    const int g3[12] = {0,1,2,13,14,15,16,17,18,29,30,31};
    const int* groups[4] = {g0, g1, g2, g3};
    const int gn[4] = {8, 4, 8, 12};
    const double invN[4]  = {1.0/8.0, 1.0/4.0, 1.0/8.0, 1.0/12.0};
    const double invN1[4] = {1.0/7.0, 1.0/3.0, 1.0/7.0, 1.0/11.0};

    double anatomy = 0.0;
    for (int g = 0; g < 4; g++) {
        const int* idx = groups[g];
        int n = gn[g];
        for (int b = 0; b < 2; b++) {
            double mean = 0.0;
            for (int k = 0; k < n; k++) mean += svol[b * 32 + idx[k]];
            mean *= invN[g];
            double ss = 0.0;
            for (int k = 0; k < n; k++) {
                double dv = svol[b * 32 + idx[k]] - mean;
                ss += dv * dv;
            }
            anatomy += ss * invN1[g] * 0.5;
        }
    }

    double L = (double)landmark * 10.0;
    double S = (double)spatial  *  5.0;
    double Y = (double)symmetry *  3.0;
    double A = anatomy * 7.0;
    double total = L + S + Y + A;

    out[0] = (float)L;
    out[1] = (float)S;
    out[2] = (float)Y;
    out[3] = (float)A;
    out[4] = (float)total;
}

extern "C" void kernel_launch(void* const* d_in, const int* in_sizes, int n_in,
                              void* d_out, int out_size) {
    const float* seg = (const float*)d_in[0];
    float* out = (float*)d_out;
    (void)in_sizes; (void)n_in; (void)out_size;

    reduce_slices_kernel<<<NSLICE, 256>>>(seg);
    finalize_kernel<<<1, 256>>>(out);
}

// round 4
// speedup vs baseline: 4.2446x; 1.3255x over previous
#include <cuda_runtime.h>
#include <math.h>

#define CHN   64        // B*C
#define DD    96        // depth slices per channel
#define HWN   16384     // 128*128
#define NSLICE (CHN*DD) // 6144

__device__ float g_part[NSLICE][3];   // per-slice [mass, wx, wy]

__global__ __launch_bounds__(256) void reduce_slices_kernel(const float* __restrict__ seg) {
    const int slice = blockIdx.x;                 // bc*96 + d
    const int tid = threadIdx.x;
    const float4* __restrict__ p = (const float4*)(seg + (size_t)slice * HWN) + tid;

    const float w0 = (float)((4 * tid) & 127);
    const float h0 = (float)(tid >> 5);

    float m = 0.f, u = 0.f, ts = 0.f;
#pragma unroll
    for (int k = 0; k < 16; k++) {
        float4 v = p[k * 256];
        float s4 = (v.x + v.y) + (v.z + v.w);
        float t  = fmaf(3.f, v.w, fmaf(2.f, v.z, v.y));
        m  += s4;
        u   = fmaf((float)k, s4, u);
        ts += t;
    }
    float wx = fmaf(w0, m, ts);
    float wy = fmaf(h0, m, 8.f * u);

    for (int o = 16; o; o >>= 1) {
        m  += __shfl_down_sync(0xffffffffu, m,  o);
        wx += __shfl_down_sync(0xffffffffu, wx, o);
        wy += __shfl_down_sync(0xffffffffu, wy, o);
    }
    __shared__ float sm[3][8];
    int lane = tid & 31, warp = tid >> 5;
    if (lane == 0) { sm[0][warp] = m; sm[1][warp] = wx; sm[2][warp] = wy; }
    __syncthreads();
    if (warp == 0) {
        m  = (lane < 8) ? sm[0][lane] : 0.f;
        wx = (lane < 8) ? sm[1][lane] : 0.f;
        wy = (lane < 8) ? sm[2][lane] : 0.f;
        for (int o = 4; o; o >>= 1) {
            m  += __shfl_down_sync(0xffffffffu, m,  o);
            wx += __shfl_down_sync(0xffffffffu, wx, o);
            wy += __shfl_down_sync(0xffffffffu, wy, o);
        }
        if (lane == 0) {
            g_part[slice][0] = m;
            g_part[slice][1] = wx;
            g_part[slice][2] = wy;
        }
    }
}

// Expected positions [32][3] (fp32, precomputed).
__constant__ float EXP_POS[32][3] = {
    {0.00000000f,-0.60000000f,0.7f},{0.12474701f,-0.58688856f,0.7f},
    {0.24404199f,-0.54812727f,0.7f},{0.35267115f,-0.48541020f,0.7f},
    {0.44588690f,-0.40147836f,0.7f},{0.51961524f,-0.30000000f,0.7f},
    {0.57063391f,-0.18541020f,0.7f},{0.59671314f,-0.06271708f,0.7f},
    {0.59671314f, 0.06271708f,0.7f},{0.57063391f, 0.18541020f,0.7f},
    {0.51961524f, 0.30000000f,0.7f},{0.44588690f, 0.40147836f,0.7f},
    {0.35267115f, 0.48541020f,0.7f},{0.24404199f, 0.54812727f,0.7f},
    {0.12474701f, 0.58688856f,0.7f},{0.00000000f, 0.60000000f,0.7f},
    {0.00000000f, 0.55000000f,0.3f},{0.11435143f, 0.53798118f,0.3f},
    {0.22370515f, 0.50245000f,0.3f},{0.32328189f, 0.44495935f,0.3f},
    {0.40872965f, 0.36802183f,0.3f},{0.47631397f, 0.27500000f,0.3f},
    {0.52308108f, 0.16995935f,0.3f},{0.54698704f, 0.05749065f,0.3f},
    {0.54698704f,-0.05749065f,0.3f},{0.52308108f,-0.16995935f,0.3f},
    {0.47631397f,-0.27500000f,0.3f},{0.40872965f,-0.36802183f,0.3f},
    {0.32328189f,-0.44495935f,0.3f},{0.22370515f,-0.50245000f,0.3f},
    {0.11435143f,-0.53798118f,0.3f},{0.00000000f,-0.55000000f,0.3f}};

__constant__ int ADJ_F[28] = {0,1,2,3,4,5,6, 8,9,10,11,12,13,14,
                              16,17,18,19,20,21,22, 24,25,26,27,28,29,30};
__constant__ int OPP1[16] = {0,1,2,3,4,5,6,7, 16,17,18,19,20,21,22,23};
__constant__ int OPP2[16] = {15,14,13,12,11,10,9,8, 31,30,29,28,27,26,25,24};
__constant__ int GIDX[4][12] = {
    {6,7,8,9,22,23,24,25, 0,0,0,0},
    {5,10,21,26, 0,0,0,0,0,0,0,0},
    {3,4,11,12,19,20,27,28, 0,0,0,0},
    {0,1,2,13,14,15,16,17,18,29,30,31}};
__constant__ int GN[4] = {8, 4, 8, 12};
__constant__ double GINVN[4]  = {1.0/8.0, 1.0/4.0, 1.0/8.0, 1.0/12.0};
__constant__ double GINVN1[4] = {1.0/7.0, 1.0/3.0, 1.0/7.0, 1.0/11.0};

__global__ __launch_bounds__(256) void finalize_kernel(float* __restrict__ out) {
    __shared__ float  sctr[CHN][3];
    __shared__ double svol[CHN];
    __shared__ float  wpart[3][8];
    __shared__ double an8[8];

    const int tid = threadIdx.x;
    const int ch  = tid >> 2;       // 0..63
    const int sub = tid & 3;        // 0..3, 24 slices each

    // ---- Phase A: per-channel moments, 4 threads/channel, float4 batched loads ----
    {
        const float4* q = (const float4*)&g_part[ch * DD + sub * 24][0];  // 18 float4 = 72 floats
        float4 v[18];
#pragma unroll
        for (int k = 0; k < 18; k++) v[k] = q[k];

        double m = 0.0, wx = 0.0, wy = 0.0, wz = 0.0;
        const double dbase = (double)(sub * 24);
#pragma unroll
        for (int k = 0; k < 18; k++) {
            const float* f = (const float*)&v[k];
#pragma unroll
            for (int j = 0; j < 4; j++) {
                const int idx = 4 * k + j;        // 0..71
                const int comp = idx % 3;
                const int sl = idx / 3;
                double x = (double)f[j];
                if (comp == 0) { m += x; wz += x * (dbase + (double)sl); }
                else if (comp == 1) wx += x;
                else wy += x;
            }
        }
        // reduce across 4 sub-threads (contiguous lanes)
        for (int o = 2; o; o >>= 1) {
            m  += __shfl_down_sync(0xffffffffu, m,  o, 4);
            wx += __shfl_down_sync(0xffffffffu, wx, o, 4);
            wy += __shfl_down_sync(0xffffffffu, wy, o, 4);
            wz += __shfl_down_sync(0xffffffffu, wz, o, 4);
        }
        if (sub == 0) {
            svol[ch] = m;
            double inv = (m > 0.0) ? (1.0 / m) : 0.0;
            sctr[ch][0] = (float)(wx * inv * (1.0 / 128.0));
            sctr[ch][1] = (float)(wy * inv * (1.0 / 128.0));
            sctr[ch][2] = (float)(wz * inv * (1.0 /  96.0));
        }
    }
    __syncthreads();

    // ---- Phase B: one thread per loss term ----
    float lm = 0.f, sp = 0.f, sy = 0.f;

    if (tid < 64) {
        // landmark term (b,c): tid = b*32 + c
        int c = tid & 31;
        const float* A = sctr[tid];
        float dx = A[0] - EXP_POS[c][0];
        float dy = A[1] - EXP_POS[c][1];
        float dz = A[2] - EXP_POS[c][2];
        lm = dx * dx + dy * dy + dz * dz;
    } else if (tid < 120) {
        // adjacent pair terms: 28 pairs x 2 batches
        int k = tid - 64, p = k >> 1, b = k & 1;
        int i = ADJ_F[p], j = i + 1;
        const float* A = sctr[b * 32 + i];
        const float* B = sctr[b * 32 + j];
        float dx = A[0] - B[0], dy = A[1] - B[1], dz = A[2] - B[2];
        float r = sqrtf(dx * dx + dy * dy + dz * dz) - 0.1f;
        if (r > 0.f) sp = r * 0.5f;
    } else if (tid < 152) {
        // opposing pair terms: 16 pairs x 2 batches -> xy_loss + z_loss (spatial)
        int k = tid - 120, p = k >> 1, b = k & 1;
        const float* A = sctr[b * 32 + OPP1[p]];
        const float* B = sctr[b * 32 + OPP2[p]];
        float dx = A[0] - B[0], dy = A[1] - B[1], dz = A[2] - B[2];
        sp = (dx * dx + dy * dy) * 0.25f;
        float r = 0.3f - fabsf(dz);
        if (r > 0.f) sp += r * 0.5f;
    } else if (tid < 184) {
        // symmetric pair terms: yz_loss + x_loss
        int k = tid - 152, p = k >> 1, b = k & 1;
        const float* A = sctr[b * 32 + OPP1[p]];
        const float* B = sctr[b * 32 + OPP2[p]];
        float dy = A[1] - B[1], dz = A[2] - B[2];
        float sx = A[0] + B[0];
        sy = (dy * dy + dz * dz) * 0.25f + sx * sx * 0.5f;
    } else if (tid < 192) {
        // anatomy terms: 4 groups x 2 batches (double)
        int k = tid - 184, g = k >> 1, b = k & 1;
        int n = GN[g];
        double mean = 0.0;
        for (int i = 0; i < n; i++) mean += svol[b * 32 + GIDX[g][i]];
        mean *= GINVN[g];
        double ss = 0.0;
        for (int i = 0; i < n; i++) {
            double dv = svol[b * 32 + GIDX[g][i]] - mean;
            ss += dv * dv;
        }
        an8[k] = ss * GINVN1[g] * 0.5;
    }

    // block reduce lm/sp/sy
    for (int o = 16; o; o >>= 1) {
        lm += __shfl_down_sync(0xffffffffu, lm, o);
        sp += __shfl_down_sync(0xffffffffu, sp, o);
        sy += __shfl_down_sync(0xffffffffu, sy, o);
    }
    int lane = tid & 31, warp = tid >> 5;
    if (lane == 0) { wpart[0][warp] = lm; wpart[1][warp] = sp; wpart[2][warp] = sy; }
    __syncthreads();

    if (tid == 0) {
        float L = 0.f, S = 0.f, Y = 0.f;
        for (int w = 0; w < 8; w++) { L += wpart[0][w]; S += wpart[1][w]; Y += wpart[2][w]; }
        double A = 0.0;
        for (int k = 0; k < 8; k++) A += an8[k];

        double Ld = (double)(L * (1.f / 192.f)) * 10.0;
        double Sd = (double)S * 5.0;
        double Yd = (double)Y * 3.0;
        double Ad = A * 7.0;
        double total = Ld + Sd + Yd + Ad;

        out[0] = (float)Ld;
        out[1] = (float)Sd;
        out[2] = (float)Yd;
        out[3] = (float)Ad;
        out[4] = (float)total;
    }
}

extern "C" void kernel_launch(void* const* d_in, const int* in_sizes, int n_in,
                              void* d_out, int out_size) {
    const float* seg = (const float*)d_in[0];
    float* out = (float*)d_out;
    (void)in_sizes; (void)n_in; (void)out_size;

    reduce_slices_kernel<<<NSLICE, 256>>>(seg);
    finalize_kernel<<<1, 256>>>(out);
}

// round 5
// speedup vs baseline: 4.8859x; 1.1511x over previous
#include <cuda_runtime.h>
#include <math.h>

#define CHN   64        // B*C
#define DD    96        // depth slices per channel
#define HWN   16384     // 128*128
#define NSLICE (CHN*DD) // 6144

__device__ double g_acc[CHN][4];      // [mass, wx, wy, wz] zero-init, reset in-kernel
__device__ unsigned int g_cnt = 0;    // block completion counter

// Expected positions [32][3] (fp32, precomputed).
__constant__ float EXP_POS[32][3] = {
    {0.00000000f,-0.60000000f,0.7f},{0.12474701f,-0.58688856f,0.7f},
    {0.24404199f,-0.54812727f,0.7f},{0.35267115f,-0.48541020f,0.7f},
    {0.44588690f,-0.40147836f,0.7f},{0.51961524f,-0.30000000f,0.7f},
    {0.57063391f,-0.18541020f,0.7f},{0.59671314f,-0.06271708f,0.7f},
    {0.59671314f, 0.06271708f,0.7f},{0.57063391f, 0.18541020f,0.7f},
    {0.51961524f, 0.30000000f,0.7f},{0.44588690f, 0.40147836f,0.7f},
    {0.35267115f, 0.48541020f,0.7f},{0.24404199f, 0.54812727f,0.7f},
    {0.12474701f, 0.58688856f,0.7f},{0.00000000f, 0.60000000f,0.7f},
    {0.00000000f, 0.55000000f,0.3f},{0.11435143f, 0.53798118f,0.3f},
    {0.22370515f, 0.50245000f,0.3f},{0.32328189f, 0.44495935f,0.3f},
    {0.40872965f, 0.36802183f,0.3f},{0.47631397f, 0.27500000f,0.3f},
    {0.52308108f, 0.16995935f,0.3f},{0.54698704f, 0.05749065f,0.3f},
    {0.54698704f,-0.05749065f,0.3f},{0.52308108f,-0.16995935f,0.3f},
    {0.47631397f,-0.27500000f,0.3f},{0.40872965f,-0.36802183f,0.3f},
    {0.32328189f,-0.44495935f,0.3f},{0.22370515f,-0.50245000f,0.3f},
    {0.11435143f,-0.53798118f,0.3f},{0.00000000f,-0.55000000f,0.3f}};

__constant__ int ADJ_F[28] = {0,1,2,3,4,5,6, 8,9,10,11,12,13,14,
                              16,17,18,19,20,21,22, 24,25,26,27,28,29,30};
__constant__ int OPP1[16] = {0,1,2,3,4,5,6,7, 16,17,18,19,20,21,22,23};
__constant__ int OPP2[16] = {15,14,13,12,11,10,9,8, 31,30,29,28,27,26,25,24};
__constant__ int GIDX[4][12] = {
    {6,7,8,9,22,23,24,25, 0,0,0,0},
    {5,10,21,26, 0,0,0,0,0,0,0,0},
    {3,4,11,12,19,20,27,28, 0,0,0,0},
    {0,1,2,13,14,15,16,17,18,29,30,31}};
__constant__ int GN[4] = {8, 4, 8, 12};
__constant__ double GINVN[4]  = {1.0/8.0, 1.0/4.0, 1.0/8.0, 1.0/12.0};
__constant__ double GINVN1[4] = {1.0/7.0, 1.0/3.0, 1.0/7.0, 1.0/11.0};

__global__ __launch_bounds__(256) void tooth_loss_kernel(const float* __restrict__ seg,
                                                         float* __restrict__ out) {
    const int slice = blockIdx.x;                 // bc*96 + d
    const int tid = threadIdx.x;
    const int bc = slice / DD;
    const int d  = slice - bc * DD;
    const float4* __restrict__ p = (const float4*)(seg + (size_t)slice * HWN) + tid;

    // Separable per-thread weights:
    //   elem linear idx = 4*(tid + 256k); col = (4*tid)&127 (const), row = (tid>>5)+8k
    const float w0 = (float)((4 * tid) & 127);
    const float h0 = (float)(tid >> 5);

    float m = 0.f, u = 0.f, ts = 0.f;
#pragma unroll
    for (int k = 0; k < 16; k++) {
        float4 v = p[k * 256];
        float s4 = (v.x + v.y) + (v.z + v.w);
        float t  = fmaf(3.f, v.w, fmaf(2.f, v.z, v.y));
        m  += s4;
        u   = fmaf((float)k, s4, u);
        ts += t;
    }
    float wx = fmaf(w0, m, ts);
    float wy = fmaf(h0, m, 8.f * u);

    for (int o = 16; o; o >>= 1) {
        m  += __shfl_down_sync(0xffffffffu, m,  o);
        wx += __shfl_down_sync(0xffffffffu, wx, o);
        wy += __shfl_down_sync(0xffffffffu, wy, o);
    }
    __shared__ float sm[3][8];
    __shared__ bool s_last;
    int lane = tid & 31, warp = tid >> 5;
    if (lane == 0) { sm[0][warp] = m; sm[1][warp] = wx; sm[2][warp] = wy; }
    if (tid == 0) s_last = false;
    __syncthreads();
    if (warp == 0) {
        m  = (lane < 8) ? sm[0][lane] : 0.f;
        wx = (lane < 8) ? sm[1][lane] : 0.f;
        wy = (lane < 8) ? sm[2][lane] : 0.f;
        for (int o = 4; o; o >>= 1) {
            m  += __shfl_down_sync(0xffffffffu, m,  o);
            wx += __shfl_down_sync(0xffffffffu, wx, o);
            wy += __shfl_down_sync(0xffffffffu, wy, o);
        }
        if (lane == 0) {
            atomicAdd(&g_acc[bc][0], (double)m);
            atomicAdd(&g_acc[bc][1], (double)wx);
            atomicAdd(&g_acc[bc][2], (double)wy);
            atomicAdd(&g_acc[bc][3], (double)m * (double)d);
            __threadfence();
            unsigned int old = atomicAdd(&g_cnt, 1u);
            if (old == NSLICE - 1) s_last = true;
        }
    }
    __syncthreads();
    if (!s_last) return;

    // ================= last block: finalize =================
    __threadfence();

    __shared__ float  sctr[CHN][3];
    __shared__ double svol[CHN];
    __shared__ float  wpart[3][8];
    __shared__ double an8[8];

    if (tid < CHN) {
        double mm = g_acc[tid][0];
        double ax = g_acc[tid][1];
        double ay = g_acc[tid][2];
        double az = g_acc[tid][3];
        svol[tid] = mm;
        double inv = (mm > 0.0) ? (1.0 / mm) : 0.0;
        sctr[tid][0] = (float)(ax * inv * (1.0 / 128.0));
        sctr[tid][1] = (float)(ay * inv * (1.0 / 128.0));
        sctr[tid][2] = (float)(az * inv * (1.0 /  96.0));
    }
    __syncthreads();

    // reset accumulators for the next graph replay (after all reads)
    if (tid < CHN * 4) ((double*)g_acc)[tid] = 0.0;
    if (tid == 0) g_cnt = 0;

    // ---- one thread per loss term ----
    float lm = 0.f, sp = 0.f, sy = 0.f;

    if (tid < 64) {
        int c = tid & 31;
        const float* A = sctr[tid];
        float dx = A[0] - EXP_POS[c][0];
        float dy = A[1] - EXP_POS[c][1];
        float dz = A[2] - EXP_POS[c][2];
        lm = dx * dx + dy * dy + dz * dz;
    } else if (tid < 120) {
        int k = tid - 64, pr = k >> 1, b = k & 1;
        int i = ADJ_F[pr], j = i + 1;
        const float* A = sctr[b * 32 + i];
        const float* B = sctr[b * 32 + j];
        float dx = A[0] - B[0], dy = A[1] - B[1], dz = A[2] - B[2];
        float r = sqrtf(dx * dx + dy * dy + dz * dz) - 0.1f;
        if (r > 0.f) sp = r * 0.5f;
    } else if (tid < 152) {
        int k = tid - 120, pr = k >> 1, b = k & 1;
        const float* A = sctr[b * 32 + OPP1[pr]];
        const float* B = sctr[b * 32 + OPP2[pr]];
        float dx = A[0] - B[0], dy = A[1] - B[1], dz = A[2] - B[2];
        sp = (dx * dx + dy * dy) * 0.25f;
        float r = 0.3f - fabsf(dz);
        if (r > 0.f) sp += r * 0.5f;
    } else if (tid < 184) {
        int k = tid - 152, pr = k >> 1, b = k & 1;
        const float* A = sctr[b * 32 + OPP1[pr]];
        const float* B = sctr[b * 32 + OPP2[pr]];
        float dy = A[1] - B[1], dz = A[2] - B[2];
        float sx = A[0] + B[0];
        sy = (dy * dy + dz * dz) * 0.25f + sx * sx * 0.5f;
    } else if (tid < 192) {
        int k = tid - 184, g = k >> 1, b = k & 1;
        int n = GN[g];
        double mean = 0.0;
        for (int i = 0; i < n; i++) mean += svol[b * 32 + GIDX[g][i]];
        mean *= GINVN[g];
        double ss = 0.0;
        for (int i = 0; i < n; i++) {
            double dv = svol[b * 32 + GIDX[g][i]] - mean;
            ss += dv * dv;
        }
        an8[k] = ss * GINVN1[g] * 0.5;
    }

    for (int o = 16; o; o >>= 1) {
        lm += __shfl_down_sync(0xffffffffu, lm, o);
        sp += __shfl_down_sync(0xffffffffu, sp, o);
        sy += __shfl_down_sync(0xffffffffu, sy, o);
    }
    if (lane == 0) { wpart[0][warp] = lm; wpart[1][warp] = sp; wpart[2][warp] = sy; }
    __syncthreads();

    if (tid == 0) {
        float L = 0.f, S = 0.f, Y = 0.f;
        for (int w = 0; w < 8; w++) { L += wpart[0][w]; S += wpart[1][w]; Y += wpart[2][w]; }
        double A = 0.0;
        for (int k = 0; k < 8; k++) A += an8[k];

        double Ld = (double)(L * (1.f / 192.f)) * 10.0;
        double Sd = (double)S * 5.0;
        double Yd = (double)Y * 3.0;
        double Ad = A * 7.0;
        double total = Ld + Sd + Yd + Ad;

        out[0] = (float)Ld;
        out[1] = (float)Sd;
        out[2] = (float)Yd;
        out[3] = (float)Ad;
        out[4] = (float)total;
    }
}

extern "C" void kernel_launch(void* const* d_in, const int* in_sizes, int n_in,
                              void* d_out, int out_size) {
    const float* seg = (const float*)d_in[0];
    float* out = (float*)d_out;
    (void)in_sizes; (void)n_in; (void)out_size;

    tooth_loss_kernel<<<NSLICE, 256>>>(seg, out);
}

// round 6
// speedup vs baseline: 5.0117x; 1.0257x over previous
#include <cuda_runtime.h>
#include <math.h>

#define CHN   64        // B*C
#define DD    96        // depth slices per channel
#define HWN   16384     // 128*128
#define SPC   6         // slices per CTA
#define CPC   (DD/SPC)  // CTAs per channel = 16
#define NCTA  (CHN*CPC) // 1024

__device__ double g_acc[CHN][4];      // [mass, wx, wy, wz] zero-init, reset in-kernel
__device__ unsigned int g_cnt = 0;    // block completion counter

__constant__ float EXP_POS[32][3] = {
    {0.00000000f,-0.60000000f,0.7f},{0.12474701f,-0.58688856f,0.7f},
    {0.24404199f,-0.54812727f,0.7f},{0.35267115f,-0.48541020f,0.7f},
    {0.44588690f,-0.40147836f,0.7f},{0.51961524f,-0.30000000f,0.7f},
    {0.57063391f,-0.18541020f,0.7f},{0.59671314f,-0.06271708f,0.7f},
    {0.59671314f, 0.06271708f,0.7f},{0.57063391f, 0.18541020f,0.7f},
    {0.51961524f, 0.30000000f,0.7f},{0.44588690f, 0.40147836f,0.7f},
    {0.35267115f, 0.48541020f,0.7f},{0.24404199f, 0.54812727f,0.7f},
    {0.12474701f, 0.58688856f,0.7f},{0.00000000f, 0.60000000f,0.7f},
    {0.00000000f, 0.55000000f,0.3f},{0.11435143f, 0.53798118f,0.3f},
    {0.22370515f, 0.50245000f,0.3f},{0.32328189f, 0.44495935f,0.3f},
    {0.40872965f, 0.36802183f,0.3f},{0.47631397f, 0.27500000f,0.3f},
    {0.52308108f, 0.16995935f,0.3f},{0.54698704f, 0.05749065f,0.3f},
    {0.54698704f,-0.05749065f,0.3f},{0.52308108f,-0.16995935f,0.3f},
    {0.47631397f,-0.27500000f,0.3f},{0.40872965f,-0.36802183f,0.3f},
    {0.32328189f,-0.44495935f,0.3f},{0.22370515f,-0.50245000f,0.3f},
    {0.11435143f,-0.53798118f,0.3f},{0.00000000f,-0.55000000f,0.3f}};

__constant__ int ADJ_F[28] = {0,1,2,3,4,5,6, 8,9,10,11,12,13,14,
                              16,17,18,19,20,21,22, 24,25,26,27,28,29,30};
__constant__ int OPP1[16] = {0,1,2,3,4,5,6,7, 16,17,18,19,20,21,22,23};
__constant__ int OPP2[16] = {15,14,13,12,11,10,9,8, 31,30,29,28,27,26,25,24};
__constant__ int GIDX[4][12] = {
    {6,7,8,9,22,23,24,25, 0,0,0,0},
    {5,10,21,26, 0,0,0,0,0,0,0,0},
    {3,4,11,12,19,20,27,28, 0,0,0,0},
    {0,1,2,13,14,15,16,17,18,29,30,31}};
__constant__ int GN[4] = {8, 4, 8, 12};
__constant__ double GINVN[4]  = {1.0/8.0, 1.0/4.0, 1.0/8.0, 1.0/12.0};
__constant__ double GINVN1[4] = {1.0/7.0, 1.0/3.0, 1.0/7.0, 1.0/11.0};

__global__ __launch_bounds__(256, 8) void tooth_loss_kernel(const float* __restrict__ seg,
                                                            float* __restrict__ out) {
    const int tid = threadIdx.x;
    const int bc   = blockIdx.x >> 4;            // channel 0..63
    const int grp  = blockIdx.x & 15;            // 0..15 within channel
    const int d0   = grp * SPC;                  // first slice depth

    const float4* __restrict__ p =
        (const float4*)(seg + (size_t)(bc * DD + d0) * HWN) + tid;

    // Per-thread separable weights: col = (4*tid)&127, row = (tid>>5)+8k
    const float w0 = (float)((4 * tid) & 127);
    const float h0 = (float)(tid >> 5);

    float m = 0.f, u = 0.f, ts = 0.f, wzd = 0.f;
#pragma unroll
    for (int s = 0; s < SPC; s++) {
        float ms = 0.f, us = 0.f, tss = 0.f;
#pragma unroll
        for (int k = 0; k < 16; k++) {
            float4 v = p[s * 4096 + k * 256];
            float s4 = (v.x + v.y) + (v.z + v.w);
            float t  = fmaf(3.f, v.w, fmaf(2.f, v.z, v.y));
            ms  += s4;
            us   = fmaf((float)k, s4, us);
            tss += t;
        }
        m  += ms;
        u  += us;
        ts += tss;
        wzd = fmaf((float)(d0 + s), ms, wzd);
    }
    float wx = fmaf(w0, m, ts);
    float wy = fmaf(h0, m, 8.f * u);

    // block reduce 4 values
    for (int o = 16; o; o >>= 1) {
        m   += __shfl_down_sync(0xffffffffu, m,   o);
        wx  += __shfl_down_sync(0xffffffffu, wx,  o);
        wy  += __shfl_down_sync(0xffffffffu, wy,  o);
        wzd += __shfl_down_sync(0xffffffffu, wzd, o);
    }
    __shared__ float sm[4][8];
    __shared__ bool s_last;
    int lane = tid & 31, warp = tid >> 5;
    if (lane == 0) { sm[0][warp] = m; sm[1][warp] = wx; sm[2][warp] = wy; sm[3][warp] = wzd; }
    if (tid == 0) s_last = false;
    __syncthreads();
    if (warp == 0) {
        m   = (lane < 8) ? sm[0][lane] : 0.f;
        wx  = (lane < 8) ? sm[1][lane] : 0.f;
        wy  = (lane < 8) ? sm[2][lane] : 0.f;
        wzd = (lane < 8) ? sm[3][lane] : 0.f;
        for (int o = 4; o; o >>= 1) {
            m   += __shfl_down_sync(0xffffffffu, m,   o);
            wx  += __shfl_down_sync(0xffffffffu, wx,  o);
            wy  += __shfl_down_sync(0xffffffffu, wy,  o);
            wzd += __shfl_down_sync(0xffffffffu, wzd, o);
        }
        if (lane == 0) {
            atomicAdd(&g_acc[bc][0], (double)m);
            atomicAdd(&g_acc[bc][1], (double)wx);
            atomicAdd(&g_acc[bc][2], (double)wy);
            atomicAdd(&g_acc[bc][3], (double)wzd);
            __threadfence();
            unsigned int old = atomicAdd(&g_cnt, 1u);
            if (old == NCTA - 1) s_last = true;
        }
    }
    __syncthreads();
    if (!s_last) return;

    // ================= last block: finalize =================
    __threadfence();

    __shared__ float  sctr[CHN][3];
    __shared__ double svol[CHN];
    __shared__ float  wpart[3][8];
    __shared__ double an8[8];

    if (tid < CHN) {
        double mm = g_acc[tid][0];
        double ax = g_acc[tid][1];
        double ay = g_acc[tid][2];
        double az = g_acc[tid][3];
        svol[tid] = mm;
        double inv = (mm > 0.0) ? (1.0 / mm) : 0.0;
        sctr[tid][0] = (float)(ax * inv * (1.0 / 128.0));
        sctr[tid][1] = (float)(ay * inv * (1.0 / 128.0));
        sctr[tid][2] = (float)(az * inv * (1.0 /  96.0));
    }
    __syncthreads();

    // reset for next graph replay (after all reads)
    if (tid < CHN * 4) ((double*)g_acc)[tid] = 0.0;
    if (tid == 0) g_cnt = 0;

    float lm = 0.f, sp = 0.f, sy = 0.f;

    if (tid < 64) {
        int c = tid & 31;
        const float* A = sctr[tid];
        float dx = A[0] - EXP_POS[c][0];
        float dy = A[1] - EXP_POS[c][1];
        float dz = A[2] - EXP_POS[c][2];
        lm = dx * dx + dy * dy + dz * dz;
    } else if (tid < 120) {
        int k = tid - 64, pr = k >> 1, b = k & 1;
        int i = ADJ_F[pr], j = i + 1;
        const float* A = sctr[b * 32 + i];
        const float* B = sctr[b * 32 + j];
        float dx = A[0] - B[0], dy = A[1] - B[1], dz = A[2] - B[2];
        float r = sqrtf(dx * dx + dy * dy + dz * dz) - 0.1f;
        if (r > 0.f) sp = r * 0.5f;
    } else if (tid < 152) {
        int k = tid - 120, pr = k >> 1, b = k & 1;
        const float* A = sctr[b * 32 + OPP1[pr]];
        const float* B = sctr[b * 32 + OPP2[pr]];
        float dx = A[0] - B[0], dy = A[1] - B[1], dz = A[2] - B[2];
        sp = (dx * dx + dy * dy) * 0.25f;
        float r = 0.3f - fabsf(dz);
        if (r > 0.f) sp += r * 0.5f;
    } else if (tid < 184) {
        int k = tid - 152, pr = k >> 1, b = k & 1;
        const float* A = sctr[b * 32 + OPP1[pr]];
        const float* B = sctr[b * 32 + OPP2[pr]];
        float dy = A[1] - B[1], dz = A[2] - B[2];
        float sx = A[0] + B[0];
        sy = (dy * dy + dz * dz) * 0.25f + sx * sx * 0.5f;
    } else if (tid < 192) {
        int k = tid - 184, g = k >> 1, b = k & 1;
        int n = GN[g];
        double mean = 0.0;
        for (int i = 0; i < n; i++) mean += svol[b * 32 + GIDX[g][i]];
        mean *= GINVN[g];
        double ss = 0.0;
        for (int i = 0; i < n; i++) {
            double dv = svol[b * 32 + GIDX[g][i]] - mean;
            ss += dv * dv;
        }
        an8[k] = ss * GINVN1[g] * 0.5;
    }

    for (int o = 16; o; o >>= 1) {
        lm += __shfl_down_sync(0xffffffffu, lm, o);
        sp += __shfl_down_sync(0xffffffffu, sp, o);
        sy += __shfl_down_sync(0xffffffffu, sy, o);
    }
    if (lane == 0) { wpart[0][warp] = lm; wpart[1][warp] = sp; wpart[2][warp] = sy; }
    __syncthreads();

    if (tid == 0) {
        float L = 0.f, S = 0.f, Y = 0.f;
        for (int w = 0; w < 8; w++) { L += wpart[0][w]; S += wpart[1][w]; Y += wpart[2][w]; }
        double A = 0.0;
        for (int k = 0; k < 8; k++) A += an8[k];

        double Ld = (double)(L * (1.f / 192.f)) * 10.0;
        double Sd = (double)S * 5.0;
        double Yd = (double)Y * 3.0;
        double Ad = A * 7.0;
        double total = Ld + Sd + Yd + Ad;

        out[0] = (float)Ld;
        out[1] = (float)Sd;
        out[2] = (float)Yd;
        out[3] = (float)Ad;
        out[4] = (float)total;
    }
}

extern "C" void kernel_launch(void* const* d_in, const int* in_sizes, int n_in,
                              void* d_out, int out_size) {
    const float* seg = (const float*)d_in[0];
    float* out = (float*)d_out;
    (void)in_sizes; (void)n_in; (void)out_size;

    tooth_loss_kernel<<<NCTA, 256>>>(seg, out);
}

// round 7
// speedup vs baseline: 5.0329x; 1.0042x over previous
#include <cuda_runtime.h>
#include <math.h>

#define CHN   64        // B*C
#define DD    96        // depth slices per channel
#define HWN   16384     // 128*128
#define SPC   6         // slices per CTA
#define NCTA  1024      // 64 channels * 16 CTAs/channel

__device__ double g_acc[CHN][4];      // [mass, wx, wy, wz]
__device__ unsigned int g_cnt = 0;

__constant__ float EXP_POS[32][3] = {
    {0.00000000f,-0.60000000f,0.7f},{0.12474701f,-0.58688856f,0.7f},
    {0.24404199f,-0.54812727f,0.7f},{0.35267115f,-0.48541020f,0.7f},
    {0.44588690f,-0.40147836f,0.7f},{0.51961524f,-0.30000000f,0.7f},
    {0.57063391f,-0.18541020f,0.7f},{0.59671314f,-0.06271708f,0.7f},
    {0.59671314f, 0.06271708f,0.7f},{0.57063391f, 0.18541020f,0.7f},
    {0.51961524f, 0.30000000f,0.7f},{0.44588690f, 0.40147836f,0.7f},
    {0.35267115f, 0.48541020f,0.7f},{0.24404199f, 0.54812727f,0.7f},
    {0.12474701f, 0.58688856f,0.7f},{0.00000000f, 0.60000000f,0.7f},
    {0.00000000f, 0.55000000f,0.3f},{0.11435143f, 0.53798118f,0.3f},
    {0.22370515f, 0.50245000f,0.3f},{0.32328189f, 0.44495935f,0.3f},
    {0.40872965f, 0.36802183f,0.3f},{0.47631397f, 0.27500000f,0.3f},
    {0.52308108f, 0.16995935f,0.3f},{0.54698704f, 0.05749065f,0.3f},
    {0.54698704f,-0.05749065f,0.3f},{0.52308108f,-0.16995935f,0.3f},
    {0.47631397f,-0.27500000f,0.3f},{0.40872965f,-0.36802183f,0.3f},
    {0.32328189f,-0.44495935f,0.3f},{0.22370515f,-0.50245000f,0.3f},
    {0.11435143f,-0.53798118f,0.3f},{0.00000000f,-0.55000000f,0.3f}};

__constant__ int ADJ_F[28] = {0,1,2,3,4,5,6, 8,9,10,11,12,13,14,
                              16,17,18,19,20,21,22, 24,25,26,27,28,29,30};
__constant__ int OPP1[16] = {0,1,2,3,4,5,6,7, 16,17,18,19,20,21,22,23};
__constant__ int OPP2[16] = {15,14,13,12,11,10,9,8, 31,30,29,28,27,26,25,24};
__constant__ int GIDX[4][12] = {
    {6,7,8,9,22,23,24,25, 0,0,0,0},
    {5,10,21,26, 0,0,0,0,0,0,0,0},
    {3,4,11,12,19,20,27,28, 0,0,0,0},
    {0,1,2,13,14,15,16,17,18,29,30,31}};
__constant__ int GN[4] = {8, 4, 8, 12};
__constant__ double GINVN[4]  = {1.0/8.0, 1.0/4.0, 1.0/8.0, 1.0/12.0};
__constant__ double GINVN1[4] = {1.0/7.0, 1.0/3.0, 1.0/7.0, 1.0/11.0};

__global__ __launch_bounds__(256, 8) void tooth_loss_kernel(const float* __restrict__ seg,
                                                            float* __restrict__ out) {
    const int tid = threadIdx.x;
    const int bc   = blockIdx.x >> 4;            // channel 0..63
    const int grp  = blockIdx.x & 15;            // 0..15 within channel
    const int d0   = grp * SPC;

    const float4* __restrict__ p =
        (const float4*)(seg + (size_t)(bc * DD + d0) * HWN) + tid;

    // Per-thread separable weights: col = (4*tid)&127, row = (tid>>5)+8k
    const float w0 = (float)((4 * tid) & 127);
    const float h0 = (float)(tid >> 5);

    float m = 0.f, u = 0.f, ts = 0.f, wzd = 0.f;
#pragma unroll
    for (int s = 0; s < SPC; s++) {
        // vector accumulators: short dependency chains, projections deferred
        float4 ma = make_float4(0.f, 0.f, 0.f, 0.f);   // plain sums per component
        float4 ra = make_float4(0.f, 0.f, 0.f, 0.f);   // k-weighted sums per component
#pragma unroll
        for (int k = 0; k < 16; k++) {
            float4 v = __ldcs(&p[s * 4096 + k * 256]);
            float fk = (float)k;
            ma.x += v.x;               ma.y += v.y;
            ma.z += v.z;               ma.w += v.w;
            ra.x = fmaf(fk, v.x, ra.x); ra.y = fmaf(fk, v.y, ra.y);
            ra.z = fmaf(fk, v.z, ra.z); ra.w = fmaf(fk, v.w, ra.w);
        }
        float ms  = (ma.x + ma.y) + (ma.z + ma.w);
        float us  = (ra.x + ra.y) + (ra.z + ra.w);
        float tss = fmaf(3.f, ma.w, fmaf(2.f, ma.z, ma.y));
        m  += ms;
        u  += us;
        ts += tss;
        wzd = fmaf((float)(d0 + s), ms, wzd);
    }
    float wx = fmaf(w0, m, ts);
    float wy = fmaf(h0, m, 8.f * u);

    for (int o = 16; o; o >>= 1) {
        m   += __shfl_down_sync(0xffffffffu, m,   o);
        wx  += __shfl_down_sync(0xffffffffu, wx,  o);
        wy  += __shfl_down_sync(0xffffffffu, wy,  o);
        wzd += __shfl_down_sync(0xffffffffu, wzd, o);
    }
    __shared__ float sm[4][8];
    __shared__ bool s_last;
    int lane = tid & 31, warp = tid >> 5;
    if (lane == 0) { sm[0][warp] = m; sm[1][warp] = wx; sm[2][warp] = wy; sm[3][warp] = wzd; }
    if (tid == 0) s_last = false;
    __syncthreads();
    if (warp == 0) {
        m   = (lane < 8) ? sm[0][lane] : 0.f;
        wx  = (lane < 8) ? sm[1][lane] : 0.f;
        wy  = (lane < 8) ? sm[2][lane] : 0.f;
        wzd = (lane < 8) ? sm[3][lane] : 0.f;
        for (int o = 4; o; o >>= 1) {
            m   += __shfl_down_sync(0xffffffffu, m,   o);
            wx  += __shfl_down_sync(0xffffffffu, wx,  o);
            wy  += __shfl_down_sync(0xffffffffu, wy,  o);
            wzd += __shfl_down_sync(0xffffffffu, wzd, o);
        }
        if (lane == 0) {
            atomicAdd(&g_acc[bc][0], (double)m);
            atomicAdd(&g_acc[bc][1], (double)wx);
            atomicAdd(&g_acc[bc][2], (double)wy);
            atomicAdd(&g_acc[bc][3], (double)wzd);
            __threadfence();
            unsigned int old = atomicAdd(&g_cnt, 1u);
            if (old == NCTA - 1) s_last = true;
        }
    }
    __syncthreads();
    if (!s_last) return;

    // ================= last block: finalize =================
    __threadfence();

    __shared__ float  sctr[CHN][3];
    __shared__ double svol[CHN];
    __shared__ float  wpart[3][8];
    __shared__ double an8[8];

    if (tid < CHN) {
        double mm = g_acc[tid][0];
        double ax = g_acc[tid][1];
        double ay = g_acc[tid][2];
        double az = g_acc[tid][3];
        svol[tid] = mm;
        double inv = (mm > 0.0) ? (1.0 / mm) : 0.0;
        sctr[tid][0] = (float)(ax * inv * (1.0 / 128.0));
        sctr[tid][1] = (float)(ay * inv * (1.0 / 128.0));
        sctr[tid][2] = (float)(az * inv * (1.0 /  96.0));
    }
    __syncthreads();

    if (tid < CHN * 4) ((double*)g_acc)[tid] = 0.0;
    if (tid == 0) g_cnt = 0;

    float lm = 0.f, sp = 0.f, sy = 0.f;

    if (tid < 64) {
        int c = tid & 31;
        const float* A = sctr[tid];
        float dx = A[0] - EXP_POS[c][0];
        float dy = A[1] - EXP_POS[c][1];
        float dz = A[2] - EXP_POS[c][2];
        lm = dx * dx + dy * dy + dz * dz;
    } else if (tid < 120) {
        int k = tid - 64, pr = k >> 1, b = k & 1;
        int i = ADJ_F[pr], j = i + 1;
        const float* A = sctr[b * 32 + i];
        const float* B = sctr[b * 32 + j];
        float dx = A[0] - B[0], dy = A[1] - B[1], dz = A[2] - B[2];
        float r = sqrtf(dx * dx + dy * dy + dz * dz) - 0.1f;
        if (r > 0.f) sp = r * 0.5f;
    } else if (tid < 152) {
        int k = tid - 120, pr = k >> 1, b = k & 1;
        const float* A = sctr[b * 32 + OPP1[pr]];
        const float* B = sctr[b * 32 + OPP2[pr]];
        float dx = A[0] - B[0], dy = A[1] - B[1], dz = A[2] - B[2];
        sp = (dx * dx + dy * dy) * 0.25f;
        float r = 0.3f - fabsf(dz);
        if (r > 0.f) sp += r * 0.5f;
    } else if (tid < 184) {
        int k = tid - 152, pr = k >> 1, b = k & 1;
        const float* A = sctr[b * 32 + OPP1[pr]];
        const float* B = sctr[b * 32 + OPP2[pr]];
        float dy = A[1] - B[1], dz = A[2] - B[2];
        float sx = A[0] + B[0];
        sy = (dy * dy + dz * dz) * 0.25f + sx * sx * 0.5f;
    } else if (tid < 192) {
        int k = tid - 184, g = k >> 1, b = k & 1;
        int n = GN[g];
        double mean = 0.0;
        for (int i = 0; i < n; i++) mean += svol[b * 32 + GIDX[g][i]];
        mean *= GINVN[g];
        double ss = 0.0;
        for (int i = 0; i < n; i++) {
            double dv = svol[b * 32 + GIDX[g][i]] - mean;
            ss += dv * dv;
        }
        an8[k] = ss * GINVN1[g] * 0.5;
    }

    for (int o = 16; o; o >>= 1) {
        lm += __shfl_down_sync(0xffffffffu, lm, o);
        sp += __shfl_down_sync(0xffffffffu, sp, o);
        sy += __shfl_down_sync(0xffffffffu, sy, o);
    }
    if (lane == 0) { wpart[0][warp] = lm; wpart[1][warp] = sp; wpart[2][warp] = sy; }
    __syncthreads();

    if (tid == 0) {
        float L = 0.f, S = 0.f, Y = 0.f;
        for (int w = 0; w < 8; w++) { L += wpart[0][w]; S += wpart[1][w]; Y += wpart[2][w]; }
        double A = 0.0;
        for (int k = 0; k < 8; k++) A += an8[k];

        double Ld = (double)(L * (1.f / 192.f)) * 10.0;
        double Sd = (double)S * 5.0;
        double Yd = (double)Y * 3.0;
        double Ad = A * 7.0;
        double total = Ld + Sd + Yd + Ad;

        out[0] = (float)Ld;
        out[1] = (float)Sd;
        out[2] = (float)Yd;
        out[3] = (float)Ad;
        out[4] = (float)total;
    }
}

extern "C" void kernel_launch(void* const* d_in, const int* in_sizes, int n_in,
                              void* d_out, int out_size) {
    const float* seg = (const float*)d_in[0];
    float* out = (float*)d_out;
    (void)in_sizes; (void)n_in; (void)out_size;

    tooth_loss_kernel<<<NCTA, 256>>>(seg, out);
}

// round 8
// speedup vs baseline: 5.0519x; 1.0038x over previous
#include <cuda_runtime.h>
#include <math.h>

#define CHN   64        // B*C
#define DD    96        // depth slices per channel
#define HWN   16384     // 128*128
#define SPC   6         // slices per CTA
#define NCTA  1024      // 64 channels * 16 CTAs/channel  (<=7 CTAs/SM, single wave)

__device__ double g_acc[CHN][4];      // [mass, wx, wy, wz]
__device__ unsigned int g_cnt = 0;

__constant__ float EXP_POS[32][3] = {
    {0.00000000f,-0.60000000f,0.7f},{0.12474701f,-0.58688856f,0.7f},
    {0.24404199f,-0.54812727f,0.7f},{0.35267115f,-0.48541020f,0.7f},
    {0.44588690f,-0.40147836f,0.7f},{0.51961524f,-0.30000000f,0.7f},
    {0.57063391f,-0.18541020f,0.7f},{0.59671314f,-0.06271708f,0.7f},
    {0.59671314f, 0.06271708f,0.7f},{0.57063391f, 0.18541020f,0.7f},
    {0.51961524f, 0.30000000f,0.7f},{0.44588690f, 0.40147836f,0.7f},
    {0.35267115f, 0.48541020f,0.7f},{0.24404199f, 0.54812727f,0.7f},
    {0.12474701f, 0.58688856f,0.7f},{0.00000000f, 0.60000000f,0.7f},
    {0.00000000f, 0.55000000f,0.3f},{0.11435143f, 0.53798118f,0.3f},
    {0.22370515f, 0.50245000f,0.3f},{0.32328189f, 0.44495935f,0.3f},
    {0.40872965f, 0.36802183f,0.3f},{0.47631397f, 0.27500000f,0.3f},
    {0.52308108f, 0.16995935f,0.3f},{0.54698704f, 0.05749065f,0.3f},
    {0.54698704f,-0.05749065f,0.3f},{0.52308108f,-0.16995935f,0.3f},
    {0.47631397f,-0.27500000f,0.3f},{0.40872965f,-0.36802183f,0.3f},
    {0.32328189f,-0.44495935f,0.3f},{0.22370515f,-0.50245000f,0.3f},
    {0.11435143f,-0.53798118f,0.3f},{0.00000000f,-0.55000000f,0.3f}};

__constant__ int ADJ_F[28] = {0,1,2,3,4,5,6, 8,9,10,11,12,13,14,
                              16,17,18,19,20,21,22, 24,25,26,27,28,29,30};
__constant__ int OPP1[16] = {0,1,2,3,4,5,6,7, 16,17,18,19,20,21,22,23};
__constant__ int OPP2[16] = {15,14,13,12,11,10,9,8, 31,30,29,28,27,26,25,24};
__constant__ int GIDX[4][12] = {
    {6,7,8,9,22,23,24,25, 0,0,0,0},
    {5,10,21,26, 0,0,0,0,0,0,0,0},
    {3,4,11,12,19,20,27,28, 0,0,0,0},
    {0,1,2,13,14,15,16,17,18,29,30,31}};
__constant__ int GN[4] = {8, 4, 8, 12};
__constant__ double GINVN[4]  = {1.0/8.0, 1.0/4.0, 1.0/8.0, 1.0/12.0};
__constant__ double GINVN1[4] = {1.0/7.0, 1.0/3.0, 1.0/7.0, 1.0/11.0};

__global__ __launch_bounds__(256, 7) void tooth_loss_kernel(const float* __restrict__ seg,
                                                            float* __restrict__ out) {
    const int tid = threadIdx.x;
    const int bc   = blockIdx.x >> 4;            // channel 0..63
    const int grp  = blockIdx.x & 15;            // 0..15 within channel
    const int d0   = grp * SPC;

    const float4* __restrict__ p =
        (const float4*)(seg + (size_t)(bc * DD + d0) * HWN) + tid;

    // Per-thread separable weights: col = (4*tid)&127, row = (tid>>5)+8k
    const float w0 = (float)((4 * tid) & 127);
    const float h0 = (float)(tid >> 5);

    float m = 0.f, u = 0.f, ts = 0.f, wzd = 0.f;
#pragma unroll
    for (int s = 0; s < SPC; s++) {
        float4 ma = make_float4(0.f, 0.f, 0.f, 0.f);   // plain sums per component
        float4 ra = make_float4(0.f, 0.f, 0.f, 0.f);   // k-weighted sums per component
#pragma unroll
        for (int k = 0; k < 16; k++) {
            float4 v = __ldcs(&p[s * 4096 + k * 256]);
            float fk = (float)k;
            ma.x += v.x;                ma.y += v.y;
            ma.z += v.z;                ma.w += v.w;
            ra.x = fmaf(fk, v.x, ra.x); ra.y = fmaf(fk, v.y, ra.y);
            ra.z = fmaf(fk, v.z, ra.z); ra.w = fmaf(fk, v.w, ra.w);
        }
        float ms  = (ma.x + ma.y) + (ma.z + ma.w);
        float us  = (ra.x + ra.y) + (ra.z + ra.w);
        float tss = fmaf(3.f, ma.w, fmaf(2.f, ma.z, ma.y));
        m  += ms;
        u  += us;
        ts += tss;
        wzd = fmaf((float)(d0 + s), ms, wzd);
    }
    float wx = fmaf(w0, m, ts);
    float wy = fmaf(h0, m, 8.f * u);

    for (int o = 16; o; o >>= 1) {
        m   += __shfl_down_sync(0xffffffffu, m,   o);
        wx  += __shfl_down_sync(0xffffffffu, wx,  o);
        wy  += __shfl_down_sync(0xffffffffu, wy,  o);
        wzd += __shfl_down_sync(0xffffffffu, wzd, o);
    }
    __shared__ float sm[4][8];
    __shared__ bool s_last;
    int lane = tid & 31, warp = tid >> 5;
    if (lane == 0) { sm[0][warp] = m; sm[1][warp] = wx; sm[2][warp] = wy; sm[3][warp] = wzd; }
    if (tid == 0) s_last = false;
    __syncthreads();
    if (warp == 0) {
        m   = (lane < 8) ? sm[0][lane] : 0.f;
        wx  = (lane < 8) ? sm[1][lane] : 0.f;
        wy  = (lane < 8) ? sm[2][lane] : 0.f;
        wzd = (lane < 8) ? sm[3][lane] : 0.f;
        for (int o = 4; o; o >>= 1) {
            m   += __shfl_down_sync(0xffffffffu, m,   o);
            wx  += __shfl_down_sync(0xffffffffu, wx,  o);
            wy  += __shfl_down_sync(0xffffffffu, wy,  o);
            wzd += __shfl_down_sync(0xffffffffu, wzd, o);
        }
        if (lane == 0) {
            atomicAdd(&g_acc[bc][0], (double)m);
            atomicAdd(&g_acc[bc][1], (double)wx);
            atomicAdd(&g_acc[bc][2], (double)wy);
            atomicAdd(&g_acc[bc][3], (double)wzd);
            __threadfence();
            unsigned int old = atomicAdd(&g_cnt, 1u);
            if (old == NCTA - 1) s_last = true;
        }
    }
    __syncthreads();
    if (!s_last) return;

    // ================= last block: finalize =================
    __threadfence();

    __shared__ float  sctr[CHN][3];
    __shared__ double svol[CHN];
    __shared__ float  wpart[3][8];
    __shared__ double an8[8];

    if (tid < CHN) {
        double mm = g_acc[tid][0];
        double ax = g_acc[tid][1];
        double ay = g_acc[tid][2];
        double az = g_acc[tid][3];
        svol[tid] = mm;
        double inv = (mm > 0.0) ? (1.0 / mm) : 0.0;
        sctr[tid][0] = (float)(ax * inv * (1.0 / 128.0));
        sctr[tid][1] = (float)(ay * inv * (1.0 / 128.0));
        sctr[tid][2] = (float)(az * inv * (1.0 /  96.0));
    }
    __syncthreads();

    // reset for next graph replay (after all reads)
    if (tid < CHN * 4) ((double*)g_acc)[tid] = 0.0;
    if (tid == 0) g_cnt = 0;

    float lm = 0.f, sp = 0.f, sy = 0.f;

    if (tid < 64) {
        int c = tid & 31;
        const float* A = sctr[tid];
        float dx = A[0] - EXP_POS[c][0];
        float dy = A[1] - EXP_POS[c][1];
        float dz = A[2] - EXP_POS[c][2];
        lm = dx * dx + dy * dy + dz * dz;
    } else if (tid < 120) {
        int k = tid - 64, pr = k >> 1, b = k & 1;
        int i = ADJ_F[pr], j = i + 1;
        const float* A = sctr[b * 32 + i];
        const float* B = sctr[b * 32 + j];
        float dx = A[0] - B[0], dy = A[1] - B[1], dz = A[2] - B[2];
        float r = sqrtf(dx * dx + dy * dy + dz * dz) - 0.1f;
        if (r > 0.f) sp = r * 0.5f;
    } else if (tid < 152) {
        int k = tid - 120, pr = k >> 1, b = k & 1;
        const float* A = sctr[b * 32 + OPP1[pr]];
        const float* B = sctr[b * 32 + OPP2[pr]];
        float dx = A[0] - B[0], dy = A[1] - B[1], dz = A[2] - B[2];
        sp = (dx * dx + dy * dy) * 0.25f;
        float r = 0.3f - fabsf(dz);
        if (r > 0.f) sp += r * 0.5f;
    } else if (tid < 184) {
        int k = tid - 152, pr = k >> 1, b = k & 1;
        const float* A = sctr[b * 32 + OPP1[pr]];
        const float* B = sctr[b * 32 + OPP2[pr]];
        float dy = A[1] - B[1], dz = A[2] - B[2];
        float sx = A[0] + B[0];
        sy = (dy * dy + dz * dz) * 0.25f + sx * sx * 0.5f;
    } else if (tid < 192) {
        int k = tid - 184, g = k >> 1, b = k & 1;
        int n = GN[g];
        double mean = 0.0;
        for (int i = 0; i < n; i++) mean += svol[b * 32 + GIDX[g][i]];
        mean *= GINVN[g];
        double ss = 0.0;
        for (int i = 0; i < n; i++) {
            double dv = svol[b * 32 + GIDX[g][i]] - mean;
            ss += dv * dv;
        }
        an8[k] = ss * GINVN1[g] * 0.5;
    }

    for (int o = 16; o; o >>= 1) {
        lm += __shfl_down_sync(0xffffffffu, lm, o);
        sp += __shfl_down_sync(0xffffffffu, sp, o);
        sy += __shfl_down_sync(0xffffffffu, sy, o);
    }
    if (lane == 0) { wpart[0][warp] = lm; wpart[1][warp] = sp; wpart[2][warp] = sy; }
    __syncthreads();

    if (tid == 0) {
        float L = 0.f, S = 0.f, Y = 0.f;
        for (int w = 0; w < 8; w++) { L += wpart[0][w]; S += wpart[1][w]; Y += wpart[2][w]; }
        double A = 0.0;
        for (int k = 0; k < 8; k++) A += an8[k];

        double Ld = (double)(L * (1.f / 192.f)) * 10.0;
        double Sd = (double)S * 5.0;
        double Yd = (double)Y * 3.0;
        double Ad = A * 7.0;
        double total = Ld + Sd + Yd + Ad;

        out[0] = (float)Ld;
        out[1] = (float)Sd;
        out[2] = (float)Yd;
        out[3] = (float)Ad;
        out[4] = (float)total;
    }
}

extern "C" void kernel_launch(void* const* d_in, const int* in_sizes, int n_in,
                              void* d_out, int out_size) {
    const float* seg = (const float*)d_in[0];
    float* out = (float*)d_out;
    (void)in_sizes; (void)n_in; (void)out_size;

    tooth_loss_kernel<<<NCTA, 256>>>(seg, out);
}

// round 9
// speedup vs baseline: 5.1865x; 1.0266x over previous
#include <cuda_runtime.h>
#include <math.h>

#define CHN   64        // B*C
#define DD    96        // depth slices per channel
#define HWN   16384     // 128*128
#define SPC   12        // slices per CTA
#define NCTA  512       // 64 channels * 8 CTAs/channel (4 CTAs/SM, single wave)
#define NTHR  512

__device__ double g_acc[CHN][4];      // [mass, wx, wy, wz]
__device__ unsigned int g_cnt = 0;

__constant__ float EXP_POS[32][3] = {
    {0.00000000f,-0.60000000f,0.7f},{0.12474701f,-0.58688856f,0.7f},
    {0.24404199f,-0.54812727f,0.7f},{0.35267115f,-0.48541020f,0.7f},
    {0.44588690f,-0.40147836f,0.7f},{0.51961524f,-0.30000000f,0.7f},
    {0.57063391f,-0.18541020f,0.7f},{0.59671314f,-0.06271708f,0.7f},
    {0.59671314f, 0.06271708f,0.7f},{0.57063391f, 0.18541020f,0.7f},
    {0.51961524f, 0.30000000f,0.7f},{0.44588690f, 0.40147836f,0.7f},
    {0.35267115f, 0.48541020f,0.7f},{0.24404199f, 0.54812727f,0.7f},
    {0.12474701f, 0.58688856f,0.7f},{0.00000000f, 0.60000000f,0.7f},
    {0.00000000f, 0.55000000f,0.3f},{0.11435143f, 0.53798118f,0.3f},
    {0.22370515f, 0.50245000f,0.3f},{0.32328189f, 0.44495935f,0.3f},
    {0.40872965f, 0.36802183f,0.3f},{0.47631397f, 0.27500000f,0.3f},
    {0.52308108f, 0.16995935f,0.3f},{0.54698704f, 0.05749065f,0.3f},
    {0.54698704f,-0.05749065f,0.3f},{0.52308108f,-0.16995935f,0.3f},
    {0.47631397f,-0.27500000f,0.3f},{0.40872965f,-0.36802183f,0.3f},
    {0.32328189f,-0.44495935f,0.3f},{0.22370515f,-0.50245000f,0.3f},
    {0.11435143f,-0.53798118f,0.3f},{0.00000000f,-0.55000000f,0.3f}};

__constant__ int ADJ_F[28] = {0,1,2,3,4,5,6, 8,9,10,11,12,13,14,
                              16,17,18,19,20,21,22, 24,25,26,27,28,29,30};
__constant__ int OPP1[16] = {0,1,2,3,4,5,6,7, 16,17,18,19,20,21,22,23};
__constant__ int OPP2[16] = {15,14,13,12,11,10,9,8, 31,30,29,28,27,26,25,24};
__constant__ int GIDX[4][12] = {
    {6,7,8,9,22,23,24,25, 0,0,0,0},
    {5,10,21,26, 0,0,0,0,0,0,0,0},
    {3,4,11,12,19,20,27,28, 0,0,0,0},
    {0,1,2,13,14,15,16,17,18,29,30,31}};
__constant__ int GN[4] = {8, 4, 8, 12};
__constant__ double GINVN[4]  = {1.0/8.0, 1.0/4.0, 1.0/8.0, 1.0/12.0};
__constant__ double GINVN1[4] = {1.0/7.0, 1.0/3.0, 1.0/7.0, 1.0/11.0};

__global__ __launch_bounds__(NTHR, 4) void tooth_loss_kernel(const float* __restrict__ seg,
                                                             float* __restrict__ out) {
    const int tid = threadIdx.x;
    const int bc   = blockIdx.x >> 3;            // channel 0..63
    const int grp  = blockIdx.x & 7;             // 0..7 within channel
    const int d0   = grp * SPC;

    // 512 threads cover one 4096-float4 slice in 8 strided steps of 512.
    const float4* __restrict__ p =
        (const float4*)(seg + (size_t)(bc * DD + d0) * HWN) + tid;

    // Per-thread separable weights:
    //   elem linear idx within slice = 4*(tid + 512k), k=0..7
    //   col = (4*tid) & 127  (constant per thread)
    //   row = (tid>>5) + 16k
    const float w0 = (float)((4 * tid) & 127);
    const float h0 = (float)(tid >> 5);

    float m = 0.f, u = 0.f, ts = 0.f, wzd = 0.f;
#pragma unroll
    for (int s = 0; s < SPC; s++) {
        float4 ma = make_float4(0.f, 0.f, 0.f, 0.f);   // plain component sums
        float4 ra = make_float4(0.f, 0.f, 0.f, 0.f);   // k-weighted component sums
#pragma unroll
        for (int k = 0; k < 8; k++) {
            float4 v = __ldcs(&p[s * 4096 + k * 512]);
            float fk = (float)k;
            ma.x += v.x;                ma.y += v.y;
            ma.z += v.z;                ma.w += v.w;
            ra.x = fmaf(fk, v.x, ra.x); ra.y = fmaf(fk, v.y, ra.y);
            ra.z = fmaf(fk, v.z, ra.z); ra.w = fmaf(fk, v.w, ra.w);
        }
        float ms  = (ma.x + ma.y) + (ma.z + ma.w);
        float us  = (ra.x + ra.y) + (ra.z + ra.w);
        float tss = fmaf(3.f, ma.w, fmaf(2.f, ma.z, ma.y));
        m  += ms;
        u  += us;                                  // row stride per k is 16 now
        ts += tss;
        wzd = fmaf((float)(d0 + s), ms, wzd);
    }
    float wx = fmaf(w0, m, ts);
    float wy = fmaf(h0, m, 16.f * u);

    for (int o = 16; o; o >>= 1) {
        m   += __shfl_down_sync(0xffffffffu, m,   o);
        wx  += __shfl_down_sync(0xffffffffu, wx,  o);
        wy  += __shfl_down_sync(0xffffffffu, wy,  o);
        wzd += __shfl_down_sync(0xffffffffu, wzd, o);
    }
    __shared__ float sm[4][16];
    __shared__ bool s_last;
    int lane = tid & 31, warp = tid >> 5;          // 16 warps
    if (lane == 0) { sm[0][warp] = m; sm[1][warp] = wx; sm[2][warp] = wy; sm[3][warp] = wzd; }
    if (tid == 0) s_last = false;
    __syncthreads();
    if (warp == 0) {
        m   = (lane < 16) ? sm[0][lane] : 0.f;
        wx  = (lane < 16) ? sm[1][lane] : 0.f;
        wy  = (lane < 16) ? sm[2][lane] : 0.f;
        wzd = (lane < 16) ? sm[3][lane] : 0.f;
        for (int o = 8; o; o >>= 1) {
            m   += __shfl_down_sync(0xffffffffu, m,   o);
            wx  += __shfl_down_sync(0xffffffffu, wx,  o);
            wy  += __shfl_down_sync(0xffffffffu, wy,  o);
            wzd += __shfl_down_sync(0xffffffffu, wzd, o);
        }
        if (lane == 0) {
            atomicAdd(&g_acc[bc][0], (double)m);
            atomicAdd(&g_acc[bc][1], (double)wx);
            atomicAdd(&g_acc[bc][2], (double)wy);
            atomicAdd(&g_acc[bc][3], (double)wzd);
            __threadfence();
            unsigned int old = atomicAdd(&g_cnt, 1u);
            if (old == NCTA - 1) s_last = true;
        }
    }
    __syncthreads();
    if (!s_last) return;

    // ================= last block: finalize =================
    __threadfence();

    __shared__ float  sctr[CHN][3];
    __shared__ double svol[CHN];
    __shared__ float  wpart[3][16];
    __shared__ double an8[8];

    if (tid < CHN) {
        double mm = g_acc[tid][0];
        double ax = g_acc[tid][1];
        double ay = g_acc[tid][2];
        double az = g_acc[tid][3];
        svol[tid] = mm;
        double inv = (mm > 0.0) ? (1.0 / mm) : 0.0;
        sctr[tid][0] = (float)(ax * inv * (1.0 / 128.0));
        sctr[tid][1] = (float)(ay * inv * (1.0 / 128.0));
        sctr[tid][2] = (float)(az * inv * (1.0 /  96.0));
    }
    __syncthreads();

    // reset for next graph replay (after all reads)
    if (tid < CHN * 4) ((double*)g_acc)[tid] = 0.0;
    if (tid == 0) g_cnt = 0;

    float lm = 0.f, sp = 0.f, sy = 0.f;

    if (tid < 64) {
        int c = tid & 31;
        const float* A = sctr[tid];
        float dx = A[0] - EXP_POS[c][0];
        float dy = A[1] - EXP_POS[c][1];
        float dz = A[2] - EXP_POS[c][2];
        lm = dx * dx + dy * dy + dz * dz;
    } else if (tid < 120) {
        int k = tid - 64, pr = k >> 1, b = k & 1;
        int i = ADJ_F[pr], j = i + 1;
        const float* A = sctr[b * 32 + i];
        const float* B = sctr[b * 32 + j];
        float dx = A[0] - B[0], dy = A[1] - B[1], dz = A[2] - B[2];
        float r = sqrtf(dx * dx + dy * dy + dz * dz) - 0.1f;
        if (r > 0.f) sp = r * 0.5f;
    } else if (tid < 152) {
        int k = tid - 120, pr = k >> 1, b = k & 1;
        const float* A = sctr[b * 32 + OPP1[pr]];
        const float* B = sctr[b * 32 + OPP2[pr]];
        float dx = A[0] - B[0], dy = A[1] - B[1], dz = A[2] - B[2];
        sp = (dx * dx + dy * dy) * 0.25f;
        float r = 0.3f - fabsf(dz);
        if (r > 0.f) sp += r * 0.5f;
    } else if (tid < 184) {
        int k = tid - 152, pr = k >> 1, b = k & 1;
        const float* A = sctr[b * 32 + OPP1[pr]];
        const float* B = sctr[b * 32 + OPP2[pr]];
        float dy = A[1] - B[1], dz = A[2] - B[2];
        float sx = A[0] + B[0];
        sy = (dy * dy + dz * dz) * 0.25f + sx * sx * 0.5f;
    } else if (tid < 192) {
        int k = tid - 184, g = k >> 1, b = k & 1;
        int n = GN[g];
        double mean = 0.0;
        for (int i = 0; i < n; i++) mean += svol[b * 32 + GIDX[g][i]];
        mean *= GINVN[g];
        double ss = 0.0;
        for (int i = 0; i < n; i++) {
            double dv = svol[b * 32 + GIDX[g][i]] - mean;
            ss += dv * dv;
        }
        an8[k] = ss * GINVN1[g] * 0.5;
    }

    for (int o = 16; o; o >>= 1) {
        lm += __shfl_down_sync(0xffffffffu, lm, o);
        sp += __shfl_down_sync(0xffffffffu, sp, o);
        sy += __shfl_down_sync(0xffffffffu, sy, o);
    }
    if (lane == 0) { wpart[0][warp] = lm; wpart[1][warp] = sp; wpart[2][warp] = sy; }
    __syncthreads();

    if (tid == 0) {
        float L = 0.f, S = 0.f, Y = 0.f;
        for (int w = 0; w < 16; w++) { L += wpart[0][w]; S += wpart[1][w]; Y += wpart[2][w]; }
        double A = 0.0;
        for (int k = 0; k < 8; k++) A += an8[k];

        double Ld = (double)(L * (1.f / 192.f)) * 10.0;
        double Sd = (double)S * 5.0;
        double Yd = (double)Y * 3.0;
        double Ad = A * 7.0;
        double total = Ld + Sd + Yd + Ad;

        out[0] = (float)Ld;
        out[1] = (float)Sd;
        out[2] = (float)Yd;
        out[3] = (float)Ad;
        out[4] = (float)total;
    }
}

extern "C" void kernel_launch(void* const* d_in, const int* in_sizes, int n_in,
                              void* d_out, int out_size) {
    const float* seg = (const float*)d_in[0];
    float* out = (float*)d_out;
    (void)in_sizes; (void)n_in; (void)out_size;

    tooth_loss_kernel<<<NCTA, NTHR>>>(seg, out);
}